// round 5
// baseline (speedup 1.0000x reference)
#include <cuda_runtime.h>
#include <cuda_bf16.h>
#include <cstdint>

#define NPTS     32768
#define KCODES   1024
#define DDIM     256
#define HWSZ     1024
#define DHW      (DDIM*HWSZ)
#define HALF_OUT 8388608
#define NT       128           // codes per tile
#define NTILES   (KCODES/NT)   // 8
#define CMAXC    32            // candidate cap per point

typedef unsigned int u32;
typedef unsigned short u16;

// Scratch (static __device__ — no allocations)
__device__ float g_xx[NPTS];
__device__ float g_cc[KCODES];
__device__ int   g_idx[NPTS];
__device__ u16   g_cand[NPTS * CMAXC];
__device__ u32   g_ccnt[NPTS];

// Smem layout (dynamic): A [128 x 264 bf16], B [128 x 264 bf16] (B region
// reused as dist [128 x 129 fp32] after each tile's MMAs complete).
#define ASTRIDE 264            // bf16 elems per A/B row (132 words -> 4-bank shift)
#define DSTRIDE 129            // fp32 elems per dist row (1-bank shift, cf-free scan)
#define S_A 0
#define S_B (128 * ASTRIDE * 2)          // 67584
#define SMEM_TOTAL (2 * 128 * ASTRIDE * 2)   // 135168

// m16n8k16 row.col f32.bf16.bf16.f32 (plain PTX — works on sm_103 non-'a')
__device__ __forceinline__ void mma_bf16(float* c, const u32* a, u32 b0, u32 b1) {
    asm volatile(
        "mma.sync.aligned.m16n8k16.row.col.f32.bf16.bf16.f32 "
        "{%0,%1,%2,%3}, {%4,%5,%6,%7}, {%8,%9}, {%0,%1,%2,%3};"
        : "+f"(c[0]), "+f"(c[1]), "+f"(c[2]), "+f"(c[3])
        : "r"(a[0]), "r"(a[1]), "r"(a[2]), "r"(a[3]), "r"(b0), "r"(b1));
}

// ---------------------------------------------------------------------------
// prep: blocks 0..3 -> cc[k]; blocks 4..131 -> xx[n]. Numerics pinned (R1).
// ---------------------------------------------------------------------------
__global__ void prep_kernel(const float* __restrict__ z, const float* __restrict__ cb) {
    int blk = blockIdx.x, tid = threadIdx.x;
    if (blk < 4) {
        int k = blk * 256 + tid;
        const float* row = cb + (size_t)k * DDIM;
        float s = 0.0f;
        for (int d = 0; d < DDIM; ++d) {
            float v = row[d];
            s = __fadd_rn(s, __fmul_rn(v, v));
        }
        g_cc[k] = s;
    } else {
        int n = (blk - 4) * 256 + tid;
        int b = n >> 10, hw = n & 1023;
        const float* base = z + (size_t)b * DHW + hw;
        float s = 0.0f;
        for (int d = 0; d < DDIM; ++d) {
            float v = base[(size_t)d * HWSZ];
            s = __fadd_rn(s, __fmul_rn(v, v));
        }
        g_xx[n] = s;
    }
}

// ---------------------------------------------------------------------------
// Pass 1: bf16 HMMA GEMM (128 pts x 1024 codes x 256) + streaming margin-
// superset candidate collection. 256 threads (8 warps), warp tile 32x64.
// ---------------------------------------------------------------------------
__global__ void __launch_bounds__(256, 1)
pass1_kernel(const float* __restrict__ z, const float* __restrict__ cb) {
    extern __shared__ char smem[];
    u16* As = (u16*)(smem + S_A);
    u16* Bs = (u16*)(smem + S_B);
    const u32* Aw = (const u32*)(smem + S_A);
    const u32* Bw = (const u32*)(smem + S_B);
    float* distS = (float*)(smem + S_B);
    __shared__ float red[256];

    const int tid  = threadIdx.x;
    const int wid  = tid >> 5;
    const int lane = tid & 31;
    const int gid  = lane >> 2;        // groupID (row within fragment)
    const int qid  = lane & 3;         // thread-in-group (k/col pairs)
    const int m0 = (wid & 3) * 32;     // warp m-offset (points)
    const int n0 = (wid >> 2) * 64;    // warp n-offset (codes)

    // cmax = sqrt(max_k cc[k])
    {
        float m = 0.0f;
        for (int k = tid; k < KCODES; k += 256) m = fmaxf(m, g_cc[k]);
        red[tid] = m;
        __syncthreads();
        if (tid < 32) {
            float v = red[tid];
            #pragma unroll
            for (int j = 1; j < 8; ++j) v = fmaxf(v, red[tid + 32 * j]);
            #pragma unroll
            for (int o = 16; o; o >>= 1) v = fmaxf(v, __shfl_xor_sync(0xFFFFFFFF, v, o));
            if (tid == 0) red[0] = v;
        }
        __syncthreads();
    }
    const float cmax = sqrtf(red[0]);

    // Stage A once: As[p][d] = bf16(z[b, d, hw0+p]).  Coalesced gmem reads.
    const int p0 = blockIdx.x * 128;
    const int b = p0 >> 10, hw0 = p0 & 1023;
    const float* zb = z + (size_t)b * DHW + hw0;
    #pragma unroll 4
    for (int idx = tid; idx < 128 * 256; idx += 256) {
        int d = idx >> 7, p = idx & 127;
        __nv_bfloat16 h = __float2bfloat16_rn(zb[(size_t)d * HWSZ + p]);
        As[p * ASTRIDE + d] = __bfloat16_as_ushort(h);
    }

    // Per-point argmin state (threads 0..127 own points)
    const int myp = tid;               // valid when tid < 128
    const int myn = p0 + myp;
    float xxn = 0.0f, margin2 = 0.0f;
    if (tid < 128) {
        xxn = g_xx[myn];
        margin2 = 2.0f * (0.021f * sqrtf(xxn) * cmax + 3e-4f);
    }
    float bmin = 3.0e38f, thr = 3.0e38f;
    int cnt = 0;

    for (int t = 0; t < NTILES; ++t) {
        __syncthreads();   // prior scan done -> safe to overwrite B/dist region
        const int k0t = t * NT;
        // Stage B tile: Bs[k][d] = bf16(cb[k0t+k][d]). float4 reads, 8B stores.
        #pragma unroll 4
        for (int idx = tid; idx < 128 * 64; idx += 256) {
            int k = idx >> 6, d4 = (idx & 63) << 2;
            float4 v = *reinterpret_cast<const float4*>(cb + (size_t)(k0t + k) * DDIM + d4);
            u32 lo = (u32)__bfloat16_as_ushort(__float2bfloat16_rn(v.x))
                   | ((u32)__bfloat16_as_ushort(__float2bfloat16_rn(v.y)) << 16);
            u32 hi = (u32)__bfloat16_as_ushort(__float2bfloat16_rn(v.z))
                   | ((u32)__bfloat16_as_ushort(__float2bfloat16_rn(v.w)) << 16);
            *(uint2*)(&Bs[k * ASTRIDE + d4]) = make_uint2(lo, hi);
        }
        __syncthreads();

        // MMA: warp tile 32x64 = 2 m16 x 8 n8, K = 256 in 16 k16-steps.
        float acc[2][8][4];
        #pragma unroll
        for (int mt = 0; mt < 2; ++mt)
            #pragma unroll
            for (int nt = 0; nt < 8; ++nt)
                #pragma unroll
                for (int r = 0; r < 4; ++r) acc[mt][nt][r] = 0.0f;

        #pragma unroll
        for (int ks = 0; ks < 16; ++ks) {
            const int kw = ks * 8 + qid;   // word col base: (ks*16 + qid*2)/2
            u32 a[2][4];
            #pragma unroll
            for (int mt = 0; mt < 2; ++mt) {
                int rA = m0 + mt * 16 + gid;
                a[mt][0] = Aw[rA * 132 + kw];
                a[mt][1] = Aw[(rA + 8) * 132 + kw];
                a[mt][2] = Aw[rA * 132 + kw + 4];
                a[mt][3] = Aw[(rA + 8) * 132 + kw + 4];
            }
            #pragma unroll
            for (int nt = 0; nt < 8; ++nt) {
                int cB = n0 + nt * 8 + gid;
                u32 b0 = Bw[cB * 132 + kw];
                u32 b1 = Bw[cB * 132 + kw + 4];
                mma_bf16(acc[0][nt], a[0], b0, b1);
                mma_bf16(acc[1][nt], a[1], b0, b1);
            }
        }
        __syncthreads();   // all warps done reading Bs -> reuse region as dist

        // Spill dot products to dist smem (row = point, col = code-in-tile)
        #pragma unroll
        for (int mt = 0; mt < 2; ++mt) {
            #pragma unroll
            for (int nt = 0; nt < 8; ++nt) {
                int r = m0 + mt * 16 + gid;
                int c = n0 + nt * 8 + qid * 2;
                distS[r * DSTRIDE + c]           = acc[mt][nt][0];
                distS[r * DSTRIDE + c + 1]       = acc[mt][nt][1];
                distS[(r + 8) * DSTRIDE + c]     = acc[mt][nt][2];
                distS[(r + 8) * DSTRIDE + c + 1] = acc[mt][nt][3];
            }
        }
        __syncthreads();

        // Scan: owner thread streams its 128 code distances (conflict-free)
        if (tid < 128) {
            const float* row = distS + myp * DSTRIDE;
            #pragma unroll 4
            for (int c = 0; c < NT; ++c) {
                float m = row[c];
                int k = k0t + c;
                float dd = (xxn + __ldg(&g_cc[k])) - 2.0f * m;
                if (dd <= thr) {
                    if (cnt < CMAXC) g_cand[(size_t)myn * CMAXC + cnt] = (u16)k;
                    cnt++;
                    if (dd < bmin) { bmin = dd; thr = dd + margin2; }
                }
            }
        }
    }
    if (tid < 128) g_ccnt[myn] = (u32)cnt;
}

// ---------------------------------------------------------------------------
// Pass 2: exact reference-ordered recompute on candidates. One sequential
// fp32 FMA chain over d=0..255 per (point,code) — bitwise = reference (R1/R2
// proven). Tie-break: lowest k among equal dd (matches jnp.argmin).
// ---------------------------------------------------------------------------
__global__ void __launch_bounds__(256)
exact_kernel(const float* __restrict__ z, const float* __restrict__ cb) {
    int n = blockIdx.x * 256 + threadIdx.x;
    int b = n >> 10, hw = n & 1023;
    const float* xb = z + (size_t)b * DHW + hw;
    float xxn = g_xx[n];
    u32 cnt = g_ccnt[n];
    float best = 3.0e38f;
    int bk = 0x7FFFFFFF;

    if (cnt <= CMAXC) {
        for (u32 i = 0; i < cnt; ++i) {
            int k = g_cand[(size_t)n * CMAXC + i];
            const float* c = cb + (size_t)k * DDIM;
            float m = 0.0f;
            #pragma unroll 8
            for (int d = 0; d < DDIM; ++d)
                m = __fmaf_rn(xb[(size_t)d * HWSZ], c[d], m);
            float t1 = __fadd_rn(xxn, g_cc[k]);
            float dd = __fadd_rn(t1, -(2.0f * m));
            if (dd < best || (dd == best && k < bk)) { best = dd; bk = k; }
        }
    } else {  // overflow fallback: full exact scan (rare)
        for (int k = 0; k < KCODES; ++k) {
            const float* c = cb + (size_t)k * DDIM;
            float m = 0.0f;
            #pragma unroll 8
            for (int d = 0; d < DDIM; ++d)
                m = __fmaf_rn(xb[(size_t)d * HWSZ], c[d], m);
            float t1 = __fadd_rn(xxn, g_cc[k]);
            float dd = __fadd_rn(t1, -(2.0f * m));
            if (dd < best) { best = dd; bk = k; }
        }
    }
    g_idx[n] = bk;
}

// ---------------------------------------------------------------------------
// Gather + straight-through outputs (unchanged, 19us).
// ---------------------------------------------------------------------------
#define GPTS 32
__global__ __launch_bounds__(256)
void gather_kernel(const float* __restrict__ z,
                   const float* __restrict__ cb,
                   float* __restrict__ out) {
    __shared__ float tile[GPTS][DDIM + 1];
    __shared__ int sidx[GPTS];

    const int tid = threadIdx.x;
    const int p0 = blockIdx.x * GPTS;
    const int b = p0 >> 10;
    const int hw0 = p0 & 1023;

    if (tid < GPTS) sidx[tid] = g_idx[p0 + tid];
    __syncthreads();

    #pragma unroll
    for (int r = 0; r < 8; ++r) {
        int lin = tid + r * 256;
        int p = lin >> 6;
        int d4 = (lin & 63) << 2;
        float4 v = *reinterpret_cast<const float4*>(cb + (size_t)sidx[p] * DDIM + d4);
        tile[p][d4 + 0] = v.x;
        tile[p][d4 + 1] = v.y;
        tile[p][d4 + 2] = v.z;
        tile[p][d4 + 3] = v.w;
    }
    __syncthreads();

    const float* zb = z + (size_t)b * DHW + hw0;
    float* o1 = out + (size_t)b * DHW + hw0;
    const int p = tid & 31;
    const int dchunk = tid >> 5;

    #pragma unroll
    for (int dd = 0; dd < DDIM; dd += 8) {
        int d = dd + dchunk;
        size_t off = (size_t)d * HWSZ + p;
        float x = zb[off];
        float q = tile[p][d];
        float t = __fadd_rn(q, -x);
        o1[off]            = __fadd_rn(x, t);
        o1[off + HALF_OUT] = q;
    }
}

// ---------------------------------------------------------------------------
extern "C" void kernel_launch(void* const* d_in, const int* in_sizes, int n_in,
                              void* d_out, int out_size) {
    const float* z  = (const float*)d_in[0];   // z_e_x  [32,256,32,32]
    const float* cb = (const float*)d_in[1];   // codebook [1024,256]
    float* out = (float*)d_out;                // [2, 32,256,32,32]

    static int smem_set = 0;
    if (!smem_set) {
        cudaFuncSetAttribute(pass1_kernel,
                             cudaFuncAttributeMaxDynamicSharedMemorySize, SMEM_TOTAL);
        smem_set = 1;
    }

    prep_kernel<<<132, 256>>>(z, cb);
    pass1_kernel<<<NPTS / 128, 256, SMEM_TOTAL>>>(z, cb);
    exact_kernel<<<NPTS / 256, 256>>>(z, cb);
    gather_kernel<<<NPTS / GPTS, 256>>>(z, cb, out);
}

// round 6
// speedup vs baseline: 11.1834x; 11.1834x over previous
#include <cuda_runtime.h>
#include <cstdint>

#define NPTS     32768
#define KCODES   1024
#define DDIM     256
#define HWSZ     1024
#define DHW      (DDIM*HWSZ)
#define HALF_OUT 8388608
#define CMAXC    64

typedef unsigned int u32;
typedef unsigned short u16;

// Scratch (static __device__ — no allocations)
__device__ u32    g_x8T[NPTS * 64];     // [256 blk][64 word][128 pt] packed int8
__device__ u32    g_c8T[KCODES * 64];   // [8 tile][64 word][128 code]
__device__ float2 g_xs[NPTS];           // (xx exact-chain, sx = max|x|)
__device__ float2 g_cs[KCODES];         // (cc exact-chain, sc = max|c|)
__device__ u16    g_cand[NPTS * CMAXC];
__device__ u32    g_ccnt[NPTS];

// ---------------------------------------------------------------------------
// prep: blocks 0..3 -> codes (cc chain, sc, pack qc transposed);
//       blocks 4..131 -> points (xx chain, sx, pack qx transposed).
// Chains use the R1/R2-proven pinned order (fadd(fmul)) — bitwise reference.
// ---------------------------------------------------------------------------
__global__ void prep_kernel(const float* __restrict__ z, const float* __restrict__ cb) {
    int blk = blockIdx.x, tid = threadIdx.x;
    if (blk < 4) {
        int k = blk * 256 + tid;
        const float* row = cb + (size_t)k * DDIM;
        float s = 0.0f, mx = 0.0f;
        for (int d = 0; d < DDIM; ++d) {
            float v = row[d];
            s = __fadd_rn(s, __fmul_rn(v, v));
            mx = fmaxf(mx, fabsf(v));
        }
        g_cs[k] = make_float2(s, mx);
        float s127 = 127.0f / fmaxf(mx, 1e-30f);
        u32 base = (u32)(k >> 7) * 8192u + (u32)(k & 127);
        for (int w = 0; w < 64; ++w) {
            u32 pk = 0;
            #pragma unroll
            for (int e = 0; e < 4; ++e) {
                int q = __float2int_rn(row[w * 4 + e] * s127);
                q = max(-127, min(127, q));
                pk |= ((u32)(q & 0xFF)) << (8 * e);
            }
            g_c8T[base + (u32)w * 128u] = pk;
        }
    } else {
        int n = (blk - 4) * 256 + tid;
        int b = n >> 10, hw = n & 1023;
        const float* base = z + (size_t)b * DHW + hw;
        float s = 0.0f, mx = 0.0f;
        for (int d = 0; d < DDIM; ++d) {
            float v = base[(size_t)d * HWSZ];
            s = __fadd_rn(s, __fmul_rn(v, v));
            mx = fmaxf(mx, fabsf(v));
        }
        g_xs[n] = make_float2(s, mx);
        g_ccnt[n] = 0;
        float s127 = 127.0f / fmaxf(mx, 1e-30f);
        u32 gb = (u32)(n >> 7) * 8192u + (u32)(n & 127);
        for (int w = 0; w < 64; ++w) {
            u32 pk = 0;
            #pragma unroll
            for (int e = 0; e < 4; ++e) {
                int q = __float2int_rn(base[(size_t)(w * 4 + e) * HWSZ] * s127);
                q = max(-127, min(127, q));
                pk |= ((u32)(q & 0xFF)) << (8 * e);
            }
            g_x8T[gb + (u32)w * 128u] = pk;
        }
    }
}

// ---------------------------------------------------------------------------
// Pass 1: int8 DP4A GEMM (128 pts x 1024 codes x K=256) + certified-margin
// candidate collection with exact global running-min threshold per point.
// 256 threads: tx = tid&15 (8 codes each), ty = tid>>4 (8 points each).
// ---------------------------------------------------------------------------
__global__ void __launch_bounds__(256, 2)
pass1_kernel() {
    extern __shared__ u32 sdyn[];          // As[64][128] | Bs[64][128]  (64KB)
    u32* As = sdyn;
    u32* Bs = sdyn + 8192;
    __shared__ float rV[128][17];
    __shared__ float gMin[128];
    __shared__ float gMar[128];

    const int tid = threadIdx.x;
    const int tx = tid & 15, ty = tid >> 4;
    const int blk = blockIdx.x, p0 = blk * 128;

    // Block-wide max of cc and sc (for Smax / Qmax)
    float mcc = 0.0f, msc = 0.0f;
    for (int k = tid; k < KCODES; k += 256) {
        float2 cs = g_cs[k];
        mcc = fmaxf(mcc, cs.x);
        msc = fmaxf(msc, cs.y);
    }
    #pragma unroll
    for (int o = 16; o; o >>= 1) {
        mcc = fmaxf(mcc, __shfl_xor_sync(0xFFFFFFFFu, mcc, o));
        msc = fmaxf(msc, __shfl_xor_sync(0xFFFFFFFFu, msc, o));
    }
    if ((tid & 31) == 0) { gMin[tid >> 5] = mcc; gMar[tid >> 5] = msc; }
    __syncthreads();
    float MCC = 0.0f, MSC = 0.0f;
    #pragma unroll
    for (int i = 0; i < 8; ++i) { MCC = fmaxf(MCC, gMin[i]); MSC = fmaxf(MSC, gMar[i]); }
    __syncthreads();
    const float Qmax = 16.0f * MSC / 254.0f;
    const float Smax = sqrtf(MCC) + Qmax;

    // Per-point margin + running-min init
    if (tid < 128) {
        float2 xs = g_xs[p0 + tid];
        float R = 16.0f * xs.y / 254.0f;
        float err = (sqrtf(xs.x) + 2.0f * R) * Qmax + R * Smax;
        gMar[tid] = 2.6f * err + 2.5e-4f;
        gMin[tid] = 3.0e38f;
    }

    // Stage A once (linear copy, coalesced, conflict-free)
    for (int l = tid; l < 8192; l += 256) As[l] = g_x8T[blk * 8192 + l];
    __syncthreads();

    for (int t = 0; t < 8; ++t) {
        // Stage B tile (previous tile's compute finished at loop-bottom sync)
        for (int l = tid; l < 8192; l += 256) Bs[l] = g_c8T[t * 8192 + l];
        __syncthreads();

        int m[8][8];
        #pragma unroll
        for (int i = 0; i < 8; ++i)
            #pragma unroll
            for (int j = 0; j < 8; ++j) m[i][j] = 0;

        #pragma unroll 4
        for (int w = 0; w < 64; ++w) {
            const u32* ar = As + w * 128 + ty * 8;
            const u32* br = Bs + w * 128 + tx * 8;
            uint4 A0 = *(const uint4*)ar;
            uint4 A1 = *(const uint4*)(ar + 4);
            uint4 B0 = *(const uint4*)br;
            uint4 B1 = *(const uint4*)(br + 4);
            int a[8] = {(int)A0.x, (int)A0.y, (int)A0.z, (int)A0.w,
                        (int)A1.x, (int)A1.y, (int)A1.z, (int)A1.w};
            int bb[8] = {(int)B0.x, (int)B0.y, (int)B0.z, (int)B0.w,
                         (int)B1.x, (int)B1.y, (int)B1.z, (int)B1.w};
            #pragma unroll
            for (int i = 0; i < 8; ++i)
                #pragma unroll
                for (int j = 0; j < 8; ++j)
                    m[i][j] = __dp4a(a[i], bb[j], m[i][j]);
        }

        // Distances (approx, fp32; margin covers all rounding) + local min
        float2 csj[8];
        #pragma unroll
        for (int j = 0; j < 8; ++j) csj[j] = g_cs[t * 128 + tx * 8 + j];
        #pragma unroll
        for (int i = 0; i < 8; ++i) {
            float2 xsi = g_xs[p0 + ty * 8 + i];
            float fx = xsi.y * (1.0f / 16129.0f);
            float lmin = 3.0e38f;
            #pragma unroll
            for (int j = 0; j < 8; ++j) {
                float dd = fmaf(-2.0f * fx * csj[j].y, (float)m[i][j],
                                xsi.x + csj[j].x);
                m[i][j] = __float_as_int(dd);   // stash dd bits in-place
                lmin = fminf(lmin, dd);
            }
            rV[ty * 8 + i][tx] = lmin;
        }
        __syncthreads();
        if (tid < 128) {
            float v = rV[tid][0];
            #pragma unroll
            for (int x = 1; x < 16; ++x) v = fminf(v, rV[tid][x]);
            gMin[tid] = fminf(gMin[tid], v);
        }
        __syncthreads();

        // Collect: dd <= runningMin + margin  (superset of true argmin)
        #pragma unroll
        for (int i = 0; i < 8; ++i) {
            int pt = ty * 8 + i;
            float thr = gMin[pt] + gMar[pt];
            int n = p0 + pt;
            #pragma unroll
            for (int j = 0; j < 8; ++j) {
                float dd = __int_as_float(m[i][j]);
                if (dd <= thr) {
                    u32 s = atomicAdd(&g_ccnt[n], 1u);
                    if (s < CMAXC)
                        g_cand[(size_t)n * CMAXC + s] = (u16)(t * 128 + tx * 8 + j);
                }
            }
        }
        __syncthreads();   // protect Bs/rV for next tile
    }
}

// ---------------------------------------------------------------------------
// Fused exact re-rank + gather. Block = 32 points. Stage x tile in smem
// (coalesced), 8 slots x 32 points re-rank candidates with the R1-proven
// bitwise-exact sequential FMA chain, lexicographic (dd,k) reduce, then
// stage chosen codebook rows and write both outputs.
// ---------------------------------------------------------------------------
__global__ void __launch_bounds__(256)
exact_gather_kernel(const float* __restrict__ z, const float* __restrict__ cb,
                    float* __restrict__ out) {
    extern __shared__ float sh[];               // xS[32][257] | tile[32][257]
    float (*xS)[257]   = (float(*)[257])sh;
    float (*tile)[257] = (float(*)[257])(sh + 32 * 257);
    __shared__ int   sidx[32];
    __shared__ float rdd[32][9];
    __shared__ int   rkk[32][9];

    const int tid = threadIdx.x;
    const int p0 = blockIdx.x * 32, b = p0 >> 10, hw0 = p0 & 1023;
    const float* zb = z + (size_t)b * DHW + hw0;

    // Stage x tile transposed (coalesced gmem, conflict-free smem)
    for (int lin = tid; lin < 32 * 256; lin += 256) {
        int d = lin >> 5, p = lin & 31;
        xS[p][d] = zb[(size_t)d * HWSZ + p];
    }
    __syncthreads();

    // Re-rank: point p = tid&31, slot s = tid>>5 (8 slots/point)
    {
        int p = tid & 31, s = tid >> 5;
        int n = p0 + p;
        u32 cnt = g_ccnt[n];
        float xxn = g_xs[n].x;
        float best = 3.0e38f;
        int bk = 0x7FFFFFFF;
        if (cnt <= CMAXC) {
            for (u32 c = s; c < cnt; c += 8) {
                int k = g_cand[(size_t)n * CMAXC + c];
                const float* crow = cb + (size_t)k * DDIM;
                float mm = 0.0f;
                #pragma unroll 8
                for (int d = 0; d < DDIM; ++d)
                    mm = __fmaf_rn(xS[p][d], crow[d], mm);
                float t1 = __fadd_rn(xxn, g_cs[k].x);
                float dd = __fadd_rn(t1, -(2.0f * mm));
                if (dd < best || (dd == best && k < bk)) { best = dd; bk = k; }
            }
        } else {   // overflow fallback: full exact scan (rare)
            for (int k = s; k < KCODES; k += 8) {
                const float* crow = cb + (size_t)k * DDIM;
                float mm = 0.0f;
                #pragma unroll 8
                for (int d = 0; d < DDIM; ++d)
                    mm = __fmaf_rn(xS[p][d], crow[d], mm);
                float t1 = __fadd_rn(xxn, g_cs[k].x);
                float dd = __fadd_rn(t1, -(2.0f * mm));
                if (dd < best || (dd == best && k < bk)) { best = dd; bk = k; }
            }
        }
        rdd[p][s] = best;
        rkk[p][s] = bk;
    }
    __syncthreads();
    if (tid < 32) {
        float bv = rdd[tid][0];
        int bk = rkk[tid][0];
        #pragma unroll
        for (int s = 1; s < 8; ++s) {
            float v = rdd[tid][s];
            int k = rkk[tid][s];
            if (v < bv || (v == bv && k < bk)) { bv = v; bk = k; }
        }
        sidx[tid] = bk;
    }
    __syncthreads();

    // Stage chosen codebook rows
    #pragma unroll
    for (int r = 0; r < 8; ++r) {
        int lin = tid + r * 256;
        int p = lin >> 6;
        int d4 = (lin & 63) << 2;
        float4 v = *reinterpret_cast<const float4*>(cb + (size_t)sidx[p] * DDIM + d4);
        tile[p][d4 + 0] = v.x;
        tile[p][d4 + 1] = v.y;
        tile[p][d4 + 2] = v.z;
        tile[p][d4 + 3] = v.w;
    }
    __syncthreads();

    // Outputs: z_q_x = fl(x + fl(q - x)); zqx_tilde = q. x from smem.
    float* o1 = out + (size_t)b * DHW + hw0;
    const int p = tid & 31;
    const int dchunk = tid >> 5;
    #pragma unroll
    for (int dd0 = 0; dd0 < DDIM; dd0 += 8) {
        int d = dd0 + dchunk;
        size_t off = (size_t)d * HWSZ + p;
        float x = xS[p][d];
        float q = tile[p][d];
        float tq = __fadd_rn(q, -x);
        o1[off]            = __fadd_rn(x, tq);
        o1[off + HALF_OUT] = q;
    }
}

// ---------------------------------------------------------------------------
extern "C" void kernel_launch(void* const* d_in, const int* in_sizes, int n_in,
                              void* d_out, int out_size) {
    const float* z  = (const float*)d_in[0];   // z_e_x  [32,256,32,32]
    const float* cb = (const float*)d_in[1];   // codebook [1024,256]
    float* out = (float*)d_out;                // [2, 32,256,32,32]

    static int inited = 0;
    if (!inited) {
        cudaFuncSetAttribute(pass1_kernel,
                             cudaFuncAttributeMaxDynamicSharedMemorySize, 65536);
        cudaFuncSetAttribute(exact_gather_kernel,
                             cudaFuncAttributeMaxDynamicSharedMemorySize, 65792);
        inited = 1;
    }

    prep_kernel<<<132, 256>>>(z, cb);
    pass1_kernel<<<NPTS / 128, 256, 65536>>>();
    exact_gather_kernel<<<NPTS / 32, 256, 65792>>>(z, cb, out);
}

// round 7
// speedup vs baseline: 13.3570x; 1.1944x over previous
#include <cuda_runtime.h>
#include <cstdint>

#define NPTS     32768
#define KCODES   1024
#define DDIM     256
#define HWSZ     1024
#define DHW      (DDIM*HWSZ)
#define HALF_OUT 8388608
#define CMAXC    64

typedef unsigned int u32;
typedef unsigned short u16;

// Scratch (static __device__ — no allocations)
__device__ u32    g_x8T[NPTS * 64];     // [256 blk][64 word][128 pt] packed int8
__device__ u32    g_c8T[KCODES * 64];   // [8 tile][64 word][128 code]
__device__ float2 g_xs[NPTS];           // (xx exact-chain, sx = max|x|)
__device__ float2 g_cs[KCODES];         // (cc exact-chain, sc = max|c|)
__device__ u16    g_cand[NPTS * CMAXC];
__device__ u32    g_ccnt[NPTS];

// ---------------------------------------------------------------------------
// prep: blocks 0..3 -> codes (cc chain, sc, pack qc transposed);
//       blocks 4..131 -> points (xx chain, sx, pack qx transposed).
// Chains use the R1/R2-proven pinned order (fadd(fmul)) — bitwise reference.
// Loads batched 16-wide for MLP; add order untouched.
// ---------------------------------------------------------------------------
__global__ void prep_kernel(const float* __restrict__ z, const float* __restrict__ cb) {
    int blk = blockIdx.x, tid = threadIdx.x;
    if (blk < 4) {
        int k = blk * 256 + tid;
        const float* row = cb + (size_t)k * DDIM;
        float s = 0.0f, mx = 0.0f;
        for (int d0 = 0; d0 < DDIM; d0 += 16) {
            float v[16];
            #pragma unroll
            for (int e = 0; e < 16; ++e) v[e] = row[d0 + e];
            #pragma unroll
            for (int e = 0; e < 16; ++e) {
                s = __fadd_rn(s, __fmul_rn(v[e], v[e]));
                mx = fmaxf(mx, fabsf(v[e]));
            }
        }
        g_cs[k] = make_float2(s, mx);
        float s127 = 127.0f / fmaxf(mx, 1e-30f);
        u32 base = (u32)(k >> 7) * 8192u + (u32)(k & 127);
        #pragma unroll 4
        for (int w = 0; w < 64; ++w) {
            u32 pk = 0;
            #pragma unroll
            for (int e = 0; e < 4; ++e) {
                int q = __float2int_rn(row[w * 4 + e] * s127);
                q = max(-127, min(127, q));
                pk |= ((u32)(q & 0xFF)) << (8 * e);
            }
            g_c8T[base + (u32)w * 128u] = pk;
        }
    } else {
        int n = (blk - 4) * 256 + tid;
        int b = n >> 10, hw = n & 1023;
        const float* base = z + (size_t)b * DHW + hw;
        float s = 0.0f, mx = 0.0f;
        for (int d0 = 0; d0 < DDIM; d0 += 16) {
            float v[16];
            #pragma unroll
            for (int e = 0; e < 16; ++e) v[e] = base[(size_t)(d0 + e) * HWSZ];
            #pragma unroll
            for (int e = 0; e < 16; ++e) {
                s = __fadd_rn(s, __fmul_rn(v[e], v[e]));
                mx = fmaxf(mx, fabsf(v[e]));
            }
        }
        g_xs[n] = make_float2(s, mx);
        g_ccnt[n] = 0;
        float s127 = 127.0f / fmaxf(mx, 1e-30f);
        u32 gb = (u32)(n >> 7) * 8192u + (u32)(n & 127);
        #pragma unroll 4
        for (int w = 0; w < 64; ++w) {
            u32 pk = 0;
            #pragma unroll
            for (int e = 0; e < 4; ++e) {
                int q = __float2int_rn(base[(size_t)(w * 4 + e) * HWSZ] * s127);
                q = max(-127, min(127, q));
                pk |= ((u32)(q & 0xFF)) << (8 * e);
            }
            g_x8T[gb + (u32)w * 128u] = pk;
        }
    }
}

// ---------------------------------------------------------------------------
// Pass 1: int8 DP4A GEMM (128 pts x 1024 codes x K=256) + certified-margin
// candidate collection with exact global running-min threshold per point.
// 256 threads: tx = tid&15 (8 codes each), ty = tid>>4 (8 points each).
// occ=1 (255-reg budget) so the 64 int accumulators + staging never spill.
// ---------------------------------------------------------------------------
__global__ void __launch_bounds__(256, 1)
pass1_kernel() {
    extern __shared__ u32 sdyn[];          // As[64][128] | Bs[64][128]  (64KB)
    u32* As = sdyn;
    u32* Bs = sdyn + 8192;
    __shared__ float rV[128][17];
    __shared__ float gMin[128];
    __shared__ float gMar[128];

    const int tid = threadIdx.x;
    const int tx = tid & 15, ty = tid >> 4;
    const int blk = blockIdx.x, p0 = blk * 128;

    // Block-wide max of cc and sc (for Smax / Qmax)
    float mcc = 0.0f, msc = 0.0f;
    for (int k = tid; k < KCODES; k += 256) {
        float2 cs = g_cs[k];
        mcc = fmaxf(mcc, cs.x);
        msc = fmaxf(msc, cs.y);
    }
    #pragma unroll
    for (int o = 16; o; o >>= 1) {
        mcc = fmaxf(mcc, __shfl_xor_sync(0xFFFFFFFFu, mcc, o));
        msc = fmaxf(msc, __shfl_xor_sync(0xFFFFFFFFu, msc, o));
    }
    if ((tid & 31) == 0) { gMin[tid >> 5] = mcc; gMar[tid >> 5] = msc; }
    __syncthreads();
    float MCC = 0.0f, MSC = 0.0f;
    #pragma unroll
    for (int i = 0; i < 8; ++i) { MCC = fmaxf(MCC, gMin[i]); MSC = fmaxf(MSC, gMar[i]); }
    __syncthreads();
    const float Qmax = 16.0f * MSC / 254.0f;
    const float Smax = sqrtf(MCC) + Qmax;

    // Per-point margin + running-min init
    if (tid < 128) {
        float2 xs = g_xs[p0 + tid];
        float R = 16.0f * xs.y / 254.0f;
        float err = (sqrtf(xs.x) + 2.0f * R) * Qmax + R * Smax;
        gMar[tid] = 2.6f * err + 2.5e-4f;
        gMin[tid] = 3.0e38f;
    }

    // Stage A once (linear copy, coalesced, conflict-free)
    for (int l = tid; l < 8192; l += 256) As[l] = g_x8T[blk * 8192 + l];
    __syncthreads();

    for (int t = 0; t < 8; ++t) {
        // Stage B tile (previous tile's compute finished at loop-bottom sync)
        for (int l = tid; l < 8192; l += 256) Bs[l] = g_c8T[t * 8192 + l];
        __syncthreads();

        int m[8][8];
        #pragma unroll
        for (int i = 0; i < 8; ++i)
            #pragma unroll
            for (int j = 0; j < 8; ++j) m[i][j] = 0;

        #pragma unroll 4
        for (int w = 0; w < 64; ++w) {
            const u32* ar = As + w * 128 + ty * 8;
            const u32* br = Bs + w * 128 + tx * 8;
            uint4 A0 = *(const uint4*)ar;
            uint4 A1 = *(const uint4*)(ar + 4);
            uint4 B0 = *(const uint4*)br;
            uint4 B1 = *(const uint4*)(br + 4);
            int a[8] = {(int)A0.x, (int)A0.y, (int)A0.z, (int)A0.w,
                        (int)A1.x, (int)A1.y, (int)A1.z, (int)A1.w};
            int bb[8] = {(int)B0.x, (int)B0.y, (int)B0.z, (int)B0.w,
                         (int)B1.x, (int)B1.y, (int)B1.z, (int)B1.w};
            #pragma unroll
            for (int i = 0; i < 8; ++i)
                #pragma unroll
                for (int j = 0; j < 8; ++j)
                    m[i][j] = __dp4a(a[i], bb[j], m[i][j]);
        }

        // Distances (approx, fp32; margin covers all rounding) + local min
        float2 csj[8];
        #pragma unroll
        for (int j = 0; j < 8; ++j) csj[j] = g_cs[t * 128 + tx * 8 + j];
        #pragma unroll
        for (int i = 0; i < 8; ++i) {
            float2 xsi = g_xs[p0 + ty * 8 + i];
            float fx = xsi.y * (1.0f / 16129.0f);
            float lmin = 3.0e38f;
            #pragma unroll
            for (int j = 0; j < 8; ++j) {
                float dd = fmaf(-2.0f * fx * csj[j].y, (float)m[i][j],
                                xsi.x + csj[j].x);
                m[i][j] = __float_as_int(dd);   // stash dd bits in-place
                lmin = fminf(lmin, dd);
            }
            rV[ty * 8 + i][tx] = lmin;
        }
        __syncthreads();
        if (tid < 128) {
            float v = rV[tid][0];
            #pragma unroll
            for (int x = 1; x < 16; ++x) v = fminf(v, rV[tid][x]);
            gMin[tid] = fminf(gMin[tid], v);
        }
        __syncthreads();

        // Collect: dd <= runningMin + margin  (superset of true argmin)
        #pragma unroll
        for (int i = 0; i < 8; ++i) {
            int pt = ty * 8 + i;
            float thr = gMin[pt] + gMar[pt];
            int n = p0 + pt;
            #pragma unroll
            for (int j = 0; j < 8; ++j) {
                float dd = __int_as_float(m[i][j]);
                if (dd <= thr) {
                    u32 s = atomicAdd(&g_ccnt[n], 1u);
                    if (s < CMAXC)
                        g_cand[(size_t)n * CMAXC + s] = (u16)(t * 128 + tx * 8 + j);
                }
            }
        }
        __syncthreads();   // protect Bs/rV for next tile
    }
}

// ---------------------------------------------------------------------------
// Fused exact re-rank + gather. Block = 32 points. Stage x tile in smem
// (coalesced), 8 slots x 32 points re-rank candidates with the R1-proven
// bitwise-exact sequential FMA chain (float4 codebook loads — 4x fewer
// gather instructions), lexicographic (dd,k) reduce, then stage chosen
// codebook rows and write both outputs.
// ---------------------------------------------------------------------------
#define XSTR 260   // fp32 row stride: 16B-aligned rows, conflict-free LDS.128
__global__ void __launch_bounds__(256)
exact_gather_kernel(const float* __restrict__ z, const float* __restrict__ cb,
                    float* __restrict__ out) {
    extern __shared__ float sh[];               // xS[32][260] | tile[32][260]
    float (*xS)[XSTR]   = (float(*)[XSTR])sh;
    float (*tile)[XSTR] = (float(*)[XSTR])(sh + 32 * XSTR);
    __shared__ int   sidx[32];
    __shared__ float rdd[32][9];
    __shared__ int   rkk[32][9];

    const int tid = threadIdx.x;
    const int p0 = blockIdx.x * 32, b = p0 >> 10, hw0 = p0 & 1023;
    const float* zb = z + (size_t)b * DHW + hw0;

    // Stage x tile transposed (coalesced gmem, conflict-free smem)
    for (int lin = tid; lin < 32 * 256; lin += 256) {
        int d = lin >> 5, p = lin & 31;
        xS[p][d] = zb[(size_t)d * HWSZ + p];
    }
    __syncthreads();

    // Re-rank: point p = tid&31, slot s = tid>>5 (8 slots/point)
    {
        int p = tid & 31, s = tid >> 5;
        int n = p0 + p;
        u32 cnt = g_ccnt[n];
        float xxn = g_xs[n].x;
        float best = 3.0e38f;
        int bk = 0x7FFFFFFF;
        if (cnt <= CMAXC) {
            for (u32 c = s; c < cnt; c += 8) {
                int k = g_cand[(size_t)n * CMAXC + c];
                const float4* crow = (const float4*)(cb + (size_t)k * DDIM);
                float mm = 0.0f;
                #pragma unroll 8
                for (int d4 = 0; d4 < DDIM / 4; ++d4) {
                    float4 cv = crow[d4];
                    const float* xp = &xS[p][d4 * 4];
                    mm = __fmaf_rn(xp[0], cv.x, mm);
                    mm = __fmaf_rn(xp[1], cv.y, mm);
                    mm = __fmaf_rn(xp[2], cv.z, mm);
                    mm = __fmaf_rn(xp[3], cv.w, mm);
                }
                float t1 = __fadd_rn(xxn, g_cs[k].x);
                float dd = __fadd_rn(t1, -(2.0f * mm));
                if (dd < best || (dd == best && k < bk)) { best = dd; bk = k; }
            }
        } else {   // overflow fallback: full exact scan (rare)
            for (int k = s; k < KCODES; k += 8) {
                const float4* crow = (const float4*)(cb + (size_t)k * DDIM);
                float mm = 0.0f;
                #pragma unroll 8
                for (int d4 = 0; d4 < DDIM / 4; ++d4) {
                    float4 cv = crow[d4];
                    const float* xp = &xS[p][d4 * 4];
                    mm = __fmaf_rn(xp[0], cv.x, mm);
                    mm = __fmaf_rn(xp[1], cv.y, mm);
                    mm = __fmaf_rn(xp[2], cv.z, mm);
                    mm = __fmaf_rn(xp[3], cv.w, mm);
                }
                float t1 = __fadd_rn(xxn, g_cs[k].x);
                float dd = __fadd_rn(t1, -(2.0f * mm));
                if (dd < best || (dd == best && k < bk)) { best = dd; bk = k; }
            }
        }
        rdd[p][s] = best;
        rkk[p][s] = bk;
    }
    __syncthreads();
    if (tid < 32) {
        float bv = rdd[tid][0];
        int bk = rkk[tid][0];
        #pragma unroll
        for (int s = 1; s < 8; ++s) {
            float v = rdd[tid][s];
            int k = rkk[tid][s];
            if (v < bv || (v == bv && k < bk)) { bv = v; bk = k; }
        }
        sidx[tid] = bk;
    }
    __syncthreads();

    // Stage chosen codebook rows
    #pragma unroll
    for (int r = 0; r < 8; ++r) {
        int lin = tid + r * 256;
        int p = lin >> 6;
        int d4 = (lin & 63) << 2;
        float4 v = *reinterpret_cast<const float4*>(cb + (size_t)sidx[p] * DDIM + d4);
        tile[p][d4 + 0] = v.x;
        tile[p][d4 + 1] = v.y;
        tile[p][d4 + 2] = v.z;
        tile[p][d4 + 3] = v.w;
    }
    __syncthreads();

    // Outputs: z_q_x = fl(x + fl(q - x)); zqx_tilde = q. x from smem.
    float* o1 = out + (size_t)b * DHW + hw0;
    const int p = tid & 31;
    const int dchunk = tid >> 5;
    #pragma unroll
    for (int dd0 = 0; dd0 < DDIM; dd0 += 8) {
        int d = dd0 + dchunk;
        size_t off = (size_t)d * HWSZ + p;
        float x = xS[p][d];
        float q = tile[p][d];
        float tq = __fadd_rn(q, -x);
        o1[off]            = __fadd_rn(x, tq);
        o1[off + HALF_OUT] = q;
    }
}

// ---------------------------------------------------------------------------
extern "C" void kernel_launch(void* const* d_in, const int* in_sizes, int n_in,
                              void* d_out, int out_size) {
    const float* z  = (const float*)d_in[0];   // z_e_x  [32,256,32,32]
    const float* cb = (const float*)d_in[1];   // codebook [1024,256]
    float* out = (float*)d_out;                // [2, 32,256,32,32]

    static int inited = 0;
    if (!inited) {
        cudaFuncSetAttribute(pass1_kernel,
                             cudaFuncAttributeMaxDynamicSharedMemorySize, 65536);
        cudaFuncSetAttribute(exact_gather_kernel,
                             cudaFuncAttributeMaxDynamicSharedMemorySize,
                             2 * 32 * XSTR * 4);
        inited = 1;
    }

    prep_kernel<<<132, 256>>>(z, cb);
    pass1_kernel<<<NPTS / 128, 256, 65536>>>();
    exact_gather_kernel<<<NPTS / 32, 256, 2 * 32 * XSTR * 4>>>(z, cb, out);
}

// round 8
// speedup vs baseline: 21.1603x; 1.5842x over previous
#include <cuda_runtime.h>
#include <cstdint>

#define NPTS     32768
#define KCODES   1024
#define DDIM     256
#define HWSZ     1024
#define DHW      (DDIM*HWSZ)
#define HALF_OUT 8388608
#define CMAXC    64

typedef unsigned int u32;
typedef unsigned short u16;

// Scratch (static __device__ — no allocations)
__device__ u32    g_c8T[KCODES * 64];   // [8 tile][64 word][128 code] packed int8
__device__ float4 g_cs4[KCODES];        // (cc exact-chain, sc=max|c|, rc=||Δc||, 0)
__device__ float  g_xx[NPTS];           // xx exact-chain
__device__ float  g_mar[NPTS];          // certified margin
__device__ float  g_minq[NPTS];         // final min of quantized dd
__device__ u16    g_cand[NPTS * CMAXC];
__device__ float  g_cdda[NPTS * CMAXC];
__device__ u32    g_ccnt[NPTS];

// ---------------------------------------------------------------------------
// code_prep: per code k — cc chain (pinned R1 order), sc, pack transposed,
// exact residual norm rc. 8 blocks x 128 threads.
// ---------------------------------------------------------------------------
__global__ void code_prep(const float* __restrict__ cb) {
    int k = blockIdx.x * 128 + threadIdx.x;
    const float* row = cb + (size_t)k * DDIM;
    float s = 0.0f, mx = 0.0f;
    for (int d0 = 0; d0 < DDIM; d0 += 16) {
        float4 v0 = *(const float4*)(row + d0);
        float4 v1 = *(const float4*)(row + d0 + 4);
        float4 v2 = *(const float4*)(row + d0 + 8);
        float4 v3 = *(const float4*)(row + d0 + 12);
        float v[16] = {v0.x, v0.y, v0.z, v0.w, v1.x, v1.y, v1.z, v1.w,
                       v2.x, v2.y, v2.z, v2.w, v3.x, v3.y, v3.z, v3.w};
        #pragma unroll
        for (int e = 0; e < 16; ++e) {
            s = __fadd_rn(s, __fmul_rn(v[e], v[e]));
            mx = fmaxf(mx, fabsf(v[e]));
        }
    }
    float mxx = fmaxf(mx, 1e-30f);
    float s127 = 127.0f / mxx;
    float cinv = mxx / 127.0f;
    float rsum = 0.0f;
    u32 base = (u32)(k >> 7) * 8192u + (u32)(k & 127);
    #pragma unroll 4
    for (int w = 0; w < 64; ++w) {
        float4 v = *(const float4*)(row + w * 4);
        float ve[4] = {v.x, v.y, v.z, v.w};
        u32 pk = 0;
        #pragma unroll
        for (int e = 0; e < 4; ++e) {
            int q = __float2int_rn(ve[e] * s127);
            q = max(-127, min(127, q));
            float diff = fmaf(-(float)q, cinv, ve[e]);
            rsum += diff * diff;
            pk |= ((u32)(q & 0xFF)) << (8 * e);
        }
        g_c8T[base + (u32)w * 128u] = pk;
    }
    g_cs4[k] = make_float4(s, mx, sqrtf(rsum) * 1.02f + 1e-7f, 0.0f);
}

// ---------------------------------------------------------------------------
// Pass 1: fused x-prep (xx chain, pack, residual, margin) + int8 DP4A GEMM
// (128 pts x 1024 codes x K=256) + certified-margin candidate collection.
// 256 threads: tx = tid&15 (8 codes), ty = tid>>4 (8 points).
// ---------------------------------------------------------------------------
__global__ void __launch_bounds__(256, 2)
pass1_kernel(const float* __restrict__ z) {
    extern __shared__ u32 sdyn[];          // As[64][128] | Bs[64][128]  (64KB)
    u32* As = sdyn;
    u32* Bs = sdyn + 8192;
    __shared__ float rV[128][17];
    __shared__ float gMin[128];
    __shared__ float sMar[128];
    __shared__ float sXX[128];
    __shared__ float sSX[128];

    const int tid = threadIdx.x;
    const int tx = tid & 15, ty = tid >> 4;
    const int blk = blockIdx.x, p0 = blk * 128;
    const int b = p0 >> 10, hw0 = p0 & 1023;
    const float* zb = z + (size_t)b * DHW + hw0;

    // Block maxes over codes: sqrt(max cc) and max rc  (scratch in gMin/sMar)
    float mcc = 0.0f, mrc = 0.0f;
    for (int k = tid; k < KCODES; k += 256) {
        float4 cs = g_cs4[k];
        mcc = fmaxf(mcc, cs.x);
        mrc = fmaxf(mrc, cs.z);
    }
    #pragma unroll
    for (int o = 16; o; o >>= 1) {
        mcc = fmaxf(mcc, __shfl_xor_sync(0xFFFFFFFFu, mcc, o));
        mrc = fmaxf(mrc, __shfl_xor_sync(0xFFFFFFFFu, mrc, o));
    }
    if ((tid & 31) == 0) { gMin[tid >> 5] = mcc; sMar[tid >> 5] = mrc; }
    __syncthreads();
    float MCC = 0.0f, MRC = 0.0f;
    #pragma unroll
    for (int i = 0; i < 8; ++i) { MCC = fmaxf(MCC, gMin[i]); MRC = fmaxf(MRC, sMar[i]); }
    __syncthreads();
    const float Smax = sqrtf(MCC);

    if (tid < 128) {
        // x-prep for point p0+tid: pinned chain, pack into As, exact residual
        const int p = tid, n = p0 + p;
        g_ccnt[n] = 0;
        float s = 0.0f, mx = 0.0f;
        for (int d0 = 0; d0 < DDIM; d0 += 16) {
            float v[16];
            #pragma unroll
            for (int e = 0; e < 16; ++e) v[e] = zb[(size_t)(d0 + e) * HWSZ + p];
            #pragma unroll
            for (int e = 0; e < 16; ++e) {
                s = __fadd_rn(s, __fmul_rn(v[e], v[e]));
                mx = fmaxf(mx, fabsf(v[e]));
            }
        }
        g_xx[n] = s;
        float mxx = fmaxf(mx, 1e-30f);
        float s127 = 127.0f / mxx;
        float xinv = mxx / 127.0f;
        float rsum = 0.0f;
        #pragma unroll 4
        for (int w = 0; w < 64; ++w) {
            u32 pk = 0;
            #pragma unroll
            for (int e = 0; e < 4; ++e) {
                float xe = zb[(size_t)(w * 4 + e) * HWSZ + p];   // L2 hit
                int q = __float2int_rn(xe * s127);
                q = max(-127, min(127, q));
                float diff = fmaf(-(float)q, xinv, xe);
                rsum += diff * diff;
                pk |= ((u32)(q & 0xFF)) << (8 * e);
            }
            As[w * 128 + p] = pk;
        }
        float rx = sqrtf(rsum) * 1.02f + 1e-7f;
        float errdot = rx * Smax + (sqrtf(s) + rx) * MRC;
        float marg = 4.2f * errdot + 2e-4f;
        sMar[p] = marg;
        g_mar[n] = marg;
        gMin[p] = 3.0e38f;
        sXX[p] = s;
        sSX[p] = mx * (1.0f / 16129.0f);   // sx/127^2
    } else {
        // Stage B tile 0 concurrently
        const uint4* src = (const uint4*)g_c8T;
        uint4* dst = (uint4*)Bs;
        for (int l = tid - 128; l < 2048; l += 128) dst[l] = src[l];
    }
    __syncthreads();

    for (int t = 0; t < 8; ++t) {
        int m[8][8];
        #pragma unroll
        for (int i = 0; i < 8; ++i)
            #pragma unroll
            for (int j = 0; j < 8; ++j) m[i][j] = 0;

        #pragma unroll 4
        for (int w = 0; w < 64; ++w) {
            const u32* ar = As + w * 128 + ty * 8;
            const u32* br = Bs + w * 128 + tx * 8;
            uint4 A0 = *(const uint4*)ar;
            uint4 A1 = *(const uint4*)(ar + 4);
            uint4 B0 = *(const uint4*)br;
            uint4 B1 = *(const uint4*)(br + 4);
            int a[8] = {(int)A0.x, (int)A0.y, (int)A0.z, (int)A0.w,
                        (int)A1.x, (int)A1.y, (int)A1.z, (int)A1.w};
            int bb[8] = {(int)B0.x, (int)B0.y, (int)B0.z, (int)B0.w,
                         (int)B1.x, (int)B1.y, (int)B1.z, (int)B1.w};
            #pragma unroll
            for (int i = 0; i < 8; ++i)
                #pragma unroll
                for (int j = 0; j < 8; ++j)
                    m[i][j] = __dp4a(a[i], bb[j], m[i][j]);
        }

        // Distances + per-thread local min (j outer to keep regs lean)
        float xx8[8], sx8[8], lmin8[8];
        #pragma unroll
        for (int i = 0; i < 8; ++i) {
            xx8[i] = sXX[ty * 8 + i];
            sx8[i] = sSX[ty * 8 + i];
            lmin8[i] = 3.0e38f;
        }
        #pragma unroll
        for (int j = 0; j < 8; ++j) {
            float4 cj = g_cs4[t * 128 + tx * 8 + j];
            #pragma unroll
            for (int i = 0; i < 8; ++i) {
                float dd = fmaf(-2.0f * sx8[i] * cj.y, (float)m[i][j],
                                xx8[i] + cj.x);
                m[i][j] = __float_as_int(dd);
                lmin8[i] = fminf(lmin8[i], dd);
            }
        }
        #pragma unroll
        for (int i = 0; i < 8; ++i) rV[ty * 8 + i][tx] = lmin8[i];
        __syncthreads();
        if (tid < 128) {
            float v = rV[tid][0];
            #pragma unroll
            for (int x = 1; x < 16; ++x) v = fminf(v, rV[tid][x]);
            gMin[tid] = fminf(gMin[tid], v);
        }
        __syncthreads();

        // Collect superset; stage next B tile concurrently (Bs free post-compute)
        #pragma unroll
        for (int i = 0; i < 8; ++i) {
            int pt = ty * 8 + i;
            float thr = gMin[pt] + sMar[pt];
            int n = p0 + pt;
            #pragma unroll
            for (int j = 0; j < 8; ++j) {
                float dd = __int_as_float(m[i][j]);
                if (dd <= thr) {
                    u32 s = atomicAdd(&g_ccnt[n], 1u);
                    if (s < CMAXC) {
                        g_cand[(size_t)n * CMAXC + s] = (u16)(t * 128 + tx * 8 + j);
                        g_cdda[(size_t)n * CMAXC + s] = dd;
                    }
                }
            }
        }
        if (t < 7) {
            const uint4* src = (const uint4*)(g_c8T + (t + 1) * 8192);
            uint4* dst = (uint4*)Bs;
            for (int l = tid; l < 2048; l += 256) dst[l] = src[l];
        }
        __syncthreads();
    }
    if (tid < 128) g_minq[p0 + tid] = gMin[tid];
}

// ---------------------------------------------------------------------------
// Fused exact re-rank + gather. Filter candidates by FINAL window
// (dda <= minq + margin) before chaining — drops stale collections.
// Exact chain = R1-proven bitwise form. float4 codebook loads.
// ---------------------------------------------------------------------------
#define XSTR 260
__global__ void __launch_bounds__(256)
exact_gather_kernel(const float* __restrict__ z, const float* __restrict__ cb,
                    float* __restrict__ out) {
    extern __shared__ float sh[];               // xS[32][260] | tile[32][260]
    float (*xS)[XSTR]   = (float(*)[XSTR])sh;
    float (*tile)[XSTR] = (float(*)[XSTR])(sh + 32 * XSTR);
    __shared__ int   sidx[32];
    __shared__ float rdd[32][9];
    __shared__ int   rkk[32][9];

    const int tid = threadIdx.x;
    const int p0 = blockIdx.x * 32, b = p0 >> 10, hw0 = p0 & 1023;
    const float* zb = z + (size_t)b * DHW + hw0;

    for (int lin = tid; lin < 32 * 256; lin += 256) {
        int d = lin >> 5, p = lin & 31;
        xS[p][d] = zb[(size_t)d * HWSZ + p];
    }
    __syncthreads();

    {
        int p = tid & 31, s = tid >> 5;
        int n = p0 + p;
        u32 cnt = g_ccnt[n];
        float xxn = g_xx[n];
        float thr = g_minq[n] + g_mar[n];
        float best = 3.0e38f;
        int bk = 0x7FFFFFFF;
        if (cnt <= CMAXC) {
            for (u32 c = s; c < cnt; c += 8) {
                if (g_cdda[(size_t)n * CMAXC + c] > thr) continue;   // stale
                int k = g_cand[(size_t)n * CMAXC + c];
                const float4* crow = (const float4*)(cb + (size_t)k * DDIM);
                float mm = 0.0f;
                #pragma unroll 8
                for (int d4 = 0; d4 < DDIM / 4; ++d4) {
                    float4 cv = crow[d4];
                    const float* xp = &xS[p][d4 * 4];
                    mm = __fmaf_rn(xp[0], cv.x, mm);
                    mm = __fmaf_rn(xp[1], cv.y, mm);
                    mm = __fmaf_rn(xp[2], cv.z, mm);
                    mm = __fmaf_rn(xp[3], cv.w, mm);
                }
                float t1 = __fadd_rn(xxn, g_cs4[k].x);
                float dd = __fadd_rn(t1, -(2.0f * mm));
                if (dd < best || (dd == best && k < bk)) { best = dd; bk = k; }
            }
        } else {   // overflow fallback: full exact scan (rare)
            for (int k = s; k < KCODES; k += 8) {
                const float4* crow = (const float4*)(cb + (size_t)k * DDIM);
                float mm = 0.0f;
                #pragma unroll 8
                for (int d4 = 0; d4 < DDIM / 4; ++d4) {
                    float4 cv = crow[d4];
                    const float* xp = &xS[p][d4 * 4];
                    mm = __fmaf_rn(xp[0], cv.x, mm);
                    mm = __fmaf_rn(xp[1], cv.y, mm);
                    mm = __fmaf_rn(xp[2], cv.z, mm);
                    mm = __fmaf_rn(xp[3], cv.w, mm);
                }
                float t1 = __fadd_rn(xxn, g_cs4[k].x);
                float dd = __fadd_rn(t1, -(2.0f * mm));
                if (dd < best || (dd == best && k < bk)) { best = dd; bk = k; }
            }
        }
        rdd[p][s] = best;
        rkk[p][s] = bk;
    }
    __syncthreads();
    if (tid < 32) {
        float bv = rdd[tid][0];
        int bk = rkk[tid][0];
        #pragma unroll
        for (int s = 1; s < 8; ++s) {
            float v = rdd[tid][s];
            int k = rkk[tid][s];
            if (v < bv || (v == bv && k < bk)) { bv = v; bk = k; }
        }
        sidx[tid] = bk;
    }
    __syncthreads();

    #pragma unroll
    for (int r = 0; r < 8; ++r) {
        int lin = tid + r * 256;
        int p = lin >> 6;
        int d4 = (lin & 63) << 2;
        float4 v = *reinterpret_cast<const float4*>(cb + (size_t)sidx[p] * DDIM + d4);
        tile[p][d4 + 0] = v.x;
        tile[p][d4 + 1] = v.y;
        tile[p][d4 + 2] = v.z;
        tile[p][d4 + 3] = v.w;
    }
    __syncthreads();

    float* o1 = out + (size_t)b * DHW + hw0;
    const int p = tid & 31;
    const int dchunk = tid >> 5;
    #pragma unroll
    for (int dd0 = 0; dd0 < DDIM; dd0 += 8) {
        int d = dd0 + dchunk;
        size_t off = (size_t)d * HWSZ + p;
        float x = xS[p][d];
        float q = tile[p][d];
        float tq = __fadd_rn(q, -x);
        o1[off]            = __fadd_rn(x, tq);
        o1[off + HALF_OUT] = q;
    }
}

// ---------------------------------------------------------------------------
extern "C" void kernel_launch(void* const* d_in, const int* in_sizes, int n_in,
                              void* d_out, int out_size) {
    const float* z  = (const float*)d_in[0];   // z_e_x  [32,256,32,32]
    const float* cb = (const float*)d_in[1];   // codebook [1024,256]
    float* out = (float*)d_out;                // [2, 32,256,32,32]

    static int inited = 0;
    if (!inited) {
        cudaFuncSetAttribute(pass1_kernel,
                             cudaFuncAttributeMaxDynamicSharedMemorySize, 65536);
        cudaFuncSetAttribute(exact_gather_kernel,
                             cudaFuncAttributeMaxDynamicSharedMemorySize,
                             2 * 32 * XSTR * 4);
        inited = 1;
    }

    code_prep<<<8, 128>>>(cb);
    pass1_kernel<<<NPTS / 128, 256, 65536>>>(z);
    exact_gather_kernel<<<NPTS / 32, 256, 2 * 32 * XSTR * 4>>>(z, cb, out);
}

// round 9
// speedup vs baseline: 22.2782x; 1.0528x over previous
#include <cuda_runtime.h>
#include <cstdint>

#define NPTS     32768
#define KCODES   1024
#define DDIM     256
#define HWSZ     1024
#define DHW      (DDIM*HWSZ)
#define HALF_OUT 8388608
#define CMAXC    64

typedef unsigned int u32;
typedef unsigned short u16;
typedef unsigned long long u64;

// Scratch (static __device__ — no allocations)
__device__ u32    g_c8T[KCODES * 64];   // [8 tile][64 word][128 code] packed int8
__device__ float4 g_cs4[KCODES];        // (cc exact-chain, sc=max|c|, rc=||Δc||, 0)
__device__ float  g_xx[NPTS];
__device__ float  g_mar[NPTS];
__device__ float  g_minq[NPTS];
__device__ u16    g_cand[NPTS * CMAXC];
__device__ float  g_cdda[NPTS * CMAXC];
__device__ u32    g_ccnt[NPTS];

__device__ __forceinline__ u32 smem_u32(const void* p) {
    return (u32)__cvta_generic_to_shared(p);
}
__device__ __forceinline__ void cp_async16(u32 dst, const void* src) {
    asm volatile("cp.async.cg.shared.global [%0], [%1], 16;" :: "r"(dst), "l"(src));
}
__device__ __forceinline__ void cp_commit() { asm volatile("cp.async.commit_group;"); }
__device__ __forceinline__ void cp_wait0()  { asm volatile("cp.async.wait_group 0;" ::: "memory"); }

// ---------------------------------------------------------------------------
// code_prep: one WARP per code. Lanes parallelize max/pack/residual; lane 0
// runs the pinned-order cc chain (bitwise reference). grid 128 x 256.
// ---------------------------------------------------------------------------
__global__ void code_prep(const float* __restrict__ cb) {
    const int tid = threadIdx.x, lane = tid & 31, wid = tid >> 5;
    const int k = blockIdx.x * 8 + wid;
    const float* row = cb + (size_t)k * DDIM;

    // Lane-parallel: 8 dims per lane
    float4 va = *(const float4*)(row + lane * 8);
    float4 vb = *(const float4*)(row + lane * 8 + 4);
    float mx = fmaxf(fmaxf(fmaxf(fabsf(va.x), fabsf(va.y)), fmaxf(fabsf(va.z), fabsf(va.w))),
                     fmaxf(fmaxf(fabsf(vb.x), fabsf(vb.y)), fmaxf(fabsf(vb.z), fabsf(vb.w))));
    #pragma unroll
    for (int o = 16; o; o >>= 1) mx = fmaxf(mx, __shfl_xor_sync(0xFFFFFFFFu, mx, o));

    float mxx = fmaxf(mx, 1e-30f);
    float s127 = 127.0f / mxx;
    float cinv = mxx / 127.0f;

    float rsum = 0.0f;
    u32 base = (u32)(k >> 7) * 8192u + (u32)(k & 127);
    float vv[8] = {va.x, va.y, va.z, va.w, vb.x, vb.y, vb.z, vb.w};
    #pragma unroll
    for (int h = 0; h < 2; ++h) {
        u32 pk = 0;
        #pragma unroll
        for (int e = 0; e < 4; ++e) {
            float ve = vv[h * 4 + e];
            int q = __float2int_rn(ve * s127);
            q = max(-127, min(127, q));
            float diff = fmaf(-(float)q, cinv, ve);
            rsum += diff * diff;
            pk |= ((u32)(q & 0xFF)) << (8 * e);
        }
        g_c8T[base + (u32)(lane * 2 + h) * 128u] = pk;
    }
    #pragma unroll
    for (int o = 16; o; o >>= 1) rsum += __shfl_xor_sync(0xFFFFFFFFu, rsum, o);

    if (lane == 0) {
        // Pinned sequential cc chain (R1 order), chunked loads for MLP
        float s = 0.0f;
        for (int d0 = 0; d0 < DDIM; d0 += 16) {
            float4 w0 = *(const float4*)(row + d0);
            float4 w1 = *(const float4*)(row + d0 + 4);
            float4 w2 = *(const float4*)(row + d0 + 8);
            float4 w3 = *(const float4*)(row + d0 + 12);
            float v[16] = {w0.x, w0.y, w0.z, w0.w, w1.x, w1.y, w1.z, w1.w,
                           w2.x, w2.y, w2.z, w2.w, w3.x, w3.y, w3.z, w3.w};
            #pragma unroll
            for (int e = 0; e < 16; ++e)
                s = __fadd_rn(s, __fmul_rn(v[e], v[e]));
        }
        g_cs4[k] = make_float4(s, mx, sqrtf(rsum) * 1.02f + 1e-7f, 0.0f);
    }
}

// ---------------------------------------------------------------------------
// Pass 1: fused x-prep + int8 DP4A GEMM + certified-margin collection.
// 256 threads: tx = tid&15 (8 codes), ty = tid>>4 (8 points). The 16 tx
// lanes of a point group live in one 16-lane half-warp -> shuffle reduce.
// B tiles double-buffered via cp.async.
// ---------------------------------------------------------------------------
__global__ void __launch_bounds__(256, 2)
pass1_kernel(const float* __restrict__ z) {
    extern __shared__ u32 sdyn[];          // As[8192] | Bs0[8192] | Bs1[8192]
    u32* As = sdyn;
    u32* Bsb[2] = { sdyn + 8192, sdyn + 16384 };
    __shared__ float sMar[128], sXX[128], sSX[128], sRX[128];
    __shared__ float sred[2][8];

    const int tid = threadIdx.x;
    const int tx = tid & 15, ty = tid >> 4;
    const int blk = blockIdx.x, p0 = blk * 128;
    const int b = p0 >> 10, hw0 = p0 & 1023;
    const float* zb = z + (size_t)b * DHW + hw0;

    // Block maxes over codes: max cc, max rc
    {
        float mcc = 0.0f, mrc = 0.0f;
        for (int k = tid; k < KCODES; k += 256) {
            float4 cs = g_cs4[k];
            mcc = fmaxf(mcc, cs.x);
            mrc = fmaxf(mrc, cs.z);
        }
        #pragma unroll
        for (int o = 16; o; o >>= 1) {
            mcc = fmaxf(mcc, __shfl_xor_sync(0xFFFFFFFFu, mcc, o));
            mrc = fmaxf(mrc, __shfl_xor_sync(0xFFFFFFFFu, mrc, o));
        }
        if ((tid & 31) == 0) { sred[0][tid >> 5] = mcc; sred[1][tid >> 5] = mrc; }
    }

    // x-prep split: threads 0-127 pinned xx chains; 128-255 pack + residual.
    if (tid < 128) {
        const int p = tid, n = p0 + p;
        g_ccnt[n] = 0;
        float s = 0.0f;
        for (int d0 = 0; d0 < DDIM; d0 += 16) {
            float v[16];
            #pragma unroll
            for (int e = 0; e < 16; ++e) v[e] = zb[(size_t)(d0 + e) * HWSZ + p];
            #pragma unroll
            for (int e = 0; e < 16; ++e)
                s = __fadd_rn(s, __fmul_rn(v[e], v[e]));
        }
        g_xx[n] = s;
        sXX[p] = s;
    } else {
        const int p = tid - 128;
        float mx = 0.0f;
        for (int d0 = 0; d0 < DDIM; d0 += 16) {
            float v[16];
            #pragma unroll
            for (int e = 0; e < 16; ++e) v[e] = zb[(size_t)(d0 + e) * HWSZ + p];
            #pragma unroll
            for (int e = 0; e < 16; ++e) mx = fmaxf(mx, fabsf(v[e]));
        }
        float mxx = fmaxf(mx, 1e-30f);
        float s127 = 127.0f / mxx;
        float xinv = mxx / 127.0f;
        float rsum = 0.0f;
        #pragma unroll 4
        for (int w = 0; w < 64; ++w) {
            u32 pk = 0;
            #pragma unroll
            for (int e = 0; e < 4; ++e) {
                float xe = zb[(size_t)(w * 4 + e) * HWSZ + p];   // L2 hit
                int q = __float2int_rn(xe * s127);
                q = max(-127, min(127, q));
                float diff = fmaf(-(float)q, xinv, xe);
                rsum += diff * diff;
                pk |= ((u32)(q & 0xFF)) << (8 * e);
            }
            As[w * 128 + p] = pk;
        }
        sSX[p] = mx * (1.0f / 16129.0f);
        sRX[p] = sqrtf(rsum) * 1.02f + 1e-7f;
    }
    __syncthreads();

    float MCC = 0.0f, MRC = 0.0f;
    #pragma unroll
    for (int i = 0; i < 8; ++i) {
        MCC = fmaxf(MCC, sred[0][i]);
        MRC = fmaxf(MRC, sred[1][i]);
    }
    const float Smax = sqrtf(MCC);

    if (tid < 128) {
        const int p = tid;
        float rx = sRX[p], s = sXX[p];
        float errdot = rx * Smax + (sqrtf(s) + rx) * MRC;
        float marg = 4.2f * errdot + 2e-4f;
        sMar[p] = marg;
        g_mar[p0 + p] = marg;
    }
    // Stage B tile 0 (all threads, async)
    {
        u32 db = smem_u32(Bsb[0]);
        #pragma unroll
        for (int r = 0; r < 8; ++r)
            cp_async16(db + (u32)(r * 256 + tid) * 16u, g_c8T + (r * 256 + tid) * 4);
        cp_commit();
        cp_wait0();
    }
    __syncthreads();

    float gmin8[8];
    #pragma unroll
    for (int i = 0; i < 8; ++i) gmin8[i] = 3.0e38f;

    for (int t = 0; t < 8; ++t) {
        if (t < 7) {   // prefetch next B tile into other buffer
            u32 db = smem_u32(Bsb[(t + 1) & 1]);
            const u32* src = g_c8T + (t + 1) * 8192;
            #pragma unroll
            for (int r = 0; r < 8; ++r)
                cp_async16(db + (u32)(r * 256 + tid) * 16u, src + (r * 256 + tid) * 4);
            cp_commit();
        }
        const u32* Bt = Bsb[t & 1];

        int m[8][8];
        #pragma unroll
        for (int i = 0; i < 8; ++i)
            #pragma unroll
            for (int j = 0; j < 8; ++j) m[i][j] = 0;

        #pragma unroll 4
        for (int w = 0; w < 64; ++w) {
            const u32* ar = As + w * 128 + ty * 8;
            const u32* br = Bt + w * 128 + tx * 8;
            uint4 A0 = *(const uint4*)ar;
            uint4 A1 = *(const uint4*)(ar + 4);
            uint4 B0 = *(const uint4*)br;
            uint4 B1 = *(const uint4*)(br + 4);
            int a[8] = {(int)A0.x, (int)A0.y, (int)A0.z, (int)A0.w,
                        (int)A1.x, (int)A1.y, (int)A1.z, (int)A1.w};
            int bb[8] = {(int)B0.x, (int)B0.y, (int)B0.z, (int)B0.w,
                         (int)B1.x, (int)B1.y, (int)B1.z, (int)B1.w};
            #pragma unroll
            for (int i = 0; i < 8; ++i)
                #pragma unroll
                for (int j = 0; j < 8; ++j)
                    m[i][j] = __dp4a(a[i], bb[j], m[i][j]);
        }

        // Epilogue: distances + half-warp shuffle min (no smem, no extra sync)
        {
            float xx8[8], sx8[8], lmin8[8];
            #pragma unroll
            for (int i = 0; i < 8; ++i) {
                xx8[i] = sXX[ty * 8 + i];
                sx8[i] = sSX[ty * 8 + i];
                lmin8[i] = 3.0e38f;
            }
            #pragma unroll
            for (int j = 0; j < 8; ++j) {
                float4 cj = g_cs4[t * 128 + tx * 8 + j];
                #pragma unroll
                for (int i = 0; i < 8; ++i) {
                    float dd = fmaf(-2.0f * sx8[i] * cj.y, (float)m[i][j],
                                    xx8[i] + cj.x);
                    m[i][j] = __float_as_int(dd);
                    lmin8[i] = fminf(lmin8[i], dd);
                }
            }
            #pragma unroll
            for (int i = 0; i < 8; ++i) {
                float v = lmin8[i];
                #pragma unroll
                for (int o = 1; o < 16; o <<= 1)
                    v = fminf(v, __shfl_xor_sync(0xFFFFFFFFu, v, o));
                gmin8[i] = fminf(gmin8[i], v);
            }
            // Collect superset
            #pragma unroll
            for (int i = 0; i < 8; ++i) {
                float thr = gmin8[i] + sMar[ty * 8 + i];
                int n = p0 + ty * 8 + i;
                #pragma unroll
                for (int j = 0; j < 8; ++j) {
                    float dd = __int_as_float(m[i][j]);
                    if (dd <= thr) {
                        u32 s = atomicAdd(&g_ccnt[n], 1u);
                        if (s < CMAXC) {
                            g_cand[(size_t)n * CMAXC + s] = (u16)(t * 128 + tx * 8 + j);
                            g_cdda[(size_t)n * CMAXC + s] = dd;
                        }
                    }
                }
            }
        }
        if (t < 7) cp_wait0();
        __syncthreads();
    }
    if ((tid & 15) == 0) {
        #pragma unroll
        for (int i = 0; i < 8; ++i) g_minq[p0 + ty * 8 + i] = gmin8[i];
    }
}

// ---------------------------------------------------------------------------
// Fused exact re-rank + gather with block worklist. Survivors of the FINAL
// window go to a shared worklist; chains distributed round-robin; per-point
// winner via atomicMin on packed (dd_bits<<32)|k  (dd>0 -> bit-monotonic;
// low bits give lowest-k tie-break = jnp.argmin). Chain = R1 bitwise form.
// ---------------------------------------------------------------------------
#define XSTR 260
__global__ void __launch_bounds__(256)
exact_gather_kernel(const float* __restrict__ z, const float* __restrict__ cb,
                    float* __restrict__ out) {
    extern __shared__ float sh[];               // xS[32][260] | tile[32][260]
    float (*xS)[XSTR]   = (float(*)[XSTR])sh;
    float (*tile)[XSTR] = (float(*)[XSTR])(sh + 32 * XSTR);
    __shared__ u32 wl[2048];
    __shared__ u64 best[32];
    __shared__ int sidx[32];
    __shared__ u32 wcnt;
    __shared__ int ovf;

    const int tid = threadIdx.x;
    const int p0 = blockIdx.x * 32, b = p0 >> 10, hw0 = p0 & 1023;
    const float* zb = z + (size_t)b * DHW + hw0;

    if (tid == 0) { wcnt = 0; ovf = 0; }
    if (tid < 32) best[tid] = ~0ull;
    for (int lin = tid; lin < 32 * 256; lin += 256) {
        int d = lin >> 5, p = lin & 31;
        xS[p][d] = zb[(size_t)d * HWSZ + p];
    }
    __syncthreads();

    // Filter survivors into worklist
    {
        int p = tid & 31, s = tid >> 5;
        int n = p0 + p;
        u32 cnt = g_ccnt[n];
        if (cnt > CMAXC) {
            if (s == 0) ovf = 1;
        } else {
            float thr = g_minq[n] + g_mar[n];
            for (u32 c = s; c < cnt; c += 8) {
                if (g_cdda[(size_t)n * CMAXC + c] <= thr) {
                    u32 id = atomicAdd(&wcnt, 1u);
                    wl[id] = ((u32)p << 10) | (u32)g_cand[(size_t)n * CMAXC + c];
                }
            }
        }
    }
    __syncthreads();

    // Chains, round-robin over worklist
    {
        u32 W = wcnt;
        for (u32 i = tid; i < W; i += 256) {
            int p = wl[i] >> 10, k = wl[i] & 1023;
            const float4* crow = (const float4*)(cb + (size_t)k * DDIM);
            float mm = 0.0f;
            #pragma unroll 8
            for (int d4 = 0; d4 < DDIM / 4; ++d4) {
                float4 cv = crow[d4];
                const float* xp = &xS[p][d4 * 4];
                mm = __fmaf_rn(xp[0], cv.x, mm);
                mm = __fmaf_rn(xp[1], cv.y, mm);
                mm = __fmaf_rn(xp[2], cv.z, mm);
                mm = __fmaf_rn(xp[3], cv.w, mm);
            }
            float t1 = __fadd_rn(g_xx[p0 + p], g_cs4[k].x);
            float dd = __fadd_rn(t1, -(2.0f * mm));
            u64 pack = ((u64)(u32)__float_as_int(dd) << 32) | (u32)k;
            atomicMin(&best[p], pack);
        }
    }
    if (ovf) {   // essentially-never fallback: full exact scan for overflow pts
        int p = tid & 31, s = tid >> 5;
        int n = p0 + p;
        if (g_ccnt[n] > CMAXC) {
            for (int k = s; k < KCODES; k += 8) {
                const float4* crow = (const float4*)(cb + (size_t)k * DDIM);
                float mm = 0.0f;
                #pragma unroll 8
                for (int d4 = 0; d4 < DDIM / 4; ++d4) {
                    float4 cv = crow[d4];
                    const float* xp = &xS[p][d4 * 4];
                    mm = __fmaf_rn(xp[0], cv.x, mm);
                    mm = __fmaf_rn(xp[1], cv.y, mm);
                    mm = __fmaf_rn(xp[2], cv.z, mm);
                    mm = __fmaf_rn(xp[3], cv.w, mm);
                }
                float t1 = __fadd_rn(g_xx[n], g_cs4[k].x);
                float dd = __fadd_rn(t1, -(2.0f * mm));
                u64 pack = ((u64)(u32)__float_as_int(dd) << 32) | (u32)k;
                atomicMin(&best[p], pack);
            }
        }
    }
    __syncthreads();
    if (tid < 32) sidx[tid] = (int)(best[tid] & 1023u);
    __syncthreads();

    // Stage chosen codebook rows
    #pragma unroll
    for (int r = 0; r < 8; ++r) {
        int lin = tid + r * 256;
        int p = lin >> 6;
        int d4 = (lin & 63) << 2;
        float4 v = *reinterpret_cast<const float4*>(cb + (size_t)sidx[p] * DDIM + d4);
        tile[p][d4 + 0] = v.x;
        tile[p][d4 + 1] = v.y;
        tile[p][d4 + 2] = v.z;
        tile[p][d4 + 3] = v.w;
    }
    __syncthreads();

    // Outputs: z_q_x = fl(x + fl(q - x)); zqx_tilde = q
    float* o1 = out + (size_t)b * DHW + hw0;
    const int p = tid & 31;
    const int dchunk = tid >> 5;
    #pragma unroll
    for (int dd0 = 0; dd0 < DDIM; dd0 += 8) {
        int d = dd0 + dchunk;
        size_t off = (size_t)d * HWSZ + p;
        float x = xS[p][d];
        float q = tile[p][d];
        float tq = __fadd_rn(q, -x);
        o1[off]            = __fadd_rn(x, tq);
        o1[off + HALF_OUT] = q;
    }
}

// ---------------------------------------------------------------------------
extern "C" void kernel_launch(void* const* d_in, const int* in_sizes, int n_in,
                              void* d_out, int out_size) {
    const float* z  = (const float*)d_in[0];   // z_e_x  [32,256,32,32]
    const float* cb = (const float*)d_in[1];   // codebook [1024,256]
    float* out = (float*)d_out;                // [2, 32,256,32,32]

    static int inited = 0;
    if (!inited) {
        cudaFuncSetAttribute(pass1_kernel,
                             cudaFuncAttributeMaxDynamicSharedMemorySize, 98304);
        cudaFuncSetAttribute(exact_gather_kernel,
                             cudaFuncAttributeMaxDynamicSharedMemorySize,
                             2 * 32 * XSTR * 4);
        inited = 1;
    }

    code_prep<<<128, 256>>>(cb);
    pass1_kernel<<<NPTS / 128, 256, 98304>>>(z);
    exact_gather_kernel<<<NPTS / 32, 256, 2 * 32 * XSTR * 4>>>(z, cb, out);
}